// round 14
// baseline (speedup 1.0000x reference)
#include <cuda_runtime.h>
#include <cuda_fp16.h>
#include <cstdint>

// Problem constants
#define B_  4
#define L_  4096
#define H_  1024
#define U_  1024
#define M_  (B_*L_)          // 16384 rows

constexpr int CL = 64;            // scan chunk length
constexpr int NC = L_ / CL;       // 64 chunks per sequence

// ---------------- scratch (device globals; no allocation allowed) -------------
__device__ __half g_WiH[(size_t)U_ * H_];   // fp16 Wi              (2 MB)
__device__ __half g_WoH[(size_t)H_ * U_];   // fp16 Wo              (2 MB)
__device__ __half g_uh [(size_t)M_ * U_];   // fp16 u, then scanned x (32 MB)
__device__ float  g_v  [(size_t)B_ * NC * U_]; // chunk carries      (1 MB)
__device__ unsigned g_cnt[2];               // grid-barrier counters (reset by cvt)

// ---------------- helpers ----------------------------------------------------
__device__ __forceinline__ uint32_t smem_u32(const void* p) {
    uint32_t a;
    asm("{ .reg .u64 t; cvta.to.shared.u64 t, %1; cvt.u32.u64 %0, t; }"
        : "=r"(a) : "l"(p));
    return a;
}

__device__ __forceinline__ void cp16(uint32_t saddr, const void* g) {
    asm volatile("cp.async.cg.shared.global [%0], [%1], 16;" :: "r"(saddr), "l"(g));
}
__device__ __forceinline__ void cp_commit() {
    asm volatile("cp.async.commit_group;" ::: "memory");
}

__device__ __forceinline__ void sts128(uint32_t saddr, uint32_t r0, uint32_t r1,
                                       uint32_t r2, uint32_t r3) {
    asm volatile("st.shared.v4.b32 [%0], {%1,%2,%3,%4};"
                 :: "r"(saddr), "r"(r0), "r"(r1), "r"(r2), "r"(r3) : "memory");
}

// ldmatrix x4: 4 matrices of 8 rows x 16B (8 halves).
__device__ __forceinline__ void ldsm4(uint32_t* r, uint32_t addr) {
    asm volatile("ldmatrix.sync.aligned.m8n8.x4.shared.b16 {%0,%1,%2,%3}, [%4];"
                 : "=r"(r[0]), "=r"(r[1]), "=r"(r[2]), "=r"(r[3]) : "r"(addr));
}

// fp32-accumulate MMA
__device__ __forceinline__ void mma_f16(float* d, const uint32_t* a, const uint32_t* b) {
    asm volatile(
        "mma.sync.aligned.m16n8k16.row.col.f32.f16.f16.f32 "
        "{%0,%1,%2,%3}, {%4,%5,%6,%7}, {%8,%9}, {%0,%1,%2,%3};\n"
        : "+f"(d[0]), "+f"(d[1]), "+f"(d[2]), "+f"(d[3])
        : "r"(a[0]), "r"(a[1]), "r"(a[2]), "r"(a[3]),
          "r"(b[0]), "r"(b[1]));
}

// device-wide spin barrier (all gridDim.x blocks must be co-resident)
__device__ __forceinline__ void grid_bar(unsigned* cnt) {
    __syncthreads();
    if (threadIdx.x == 0) {
        __threadfence();
        atomicAdd(cnt, 1u);
        while (*(volatile unsigned*)cnt < gridDim.x) { __nanosleep(32); }
    }
    __syncthreads();
    __threadfence();
}

// ---------------- fp16 conversion (weights only) + barrier reset --------------
__global__ void cvt_w_kernel(const float4* __restrict__ wi,
                             const float4* __restrict__ wo)
{
    if (blockIdx.x == 0 && threadIdx.x == 0) {   // reset scan grid-barriers
        g_cnt[0] = 0;
        g_cnt[1] = 0;
    }
    const size_t n_w = (size_t)U_ * H_ / 8;      // uint4 (8-half) chunks
    size_t i = (size_t)blockIdx.x * blockDim.x + threadIdx.x;
    const size_t stride = (size_t)gridDim.x * blockDim.x;
    for (; i < 2 * n_w; i += stride) {
        const float4* src;
        __half* dst;
        size_t j;
        if (i < n_w) { src = wi; dst = g_WiH; j = i; }
        else         { src = wo; dst = g_WoH; j = i - n_w; }
        float4 a = src[2 * j], b = src[2 * j + 1];
        __half2 h[4];
        h[0] = __floats2half2_rn(a.x, a.y);
        h[1] = __floats2half2_rn(a.z, a.w);
        h[2] = __floats2half2_rn(b.x, b.y);
        h[3] = __floats2half2_rn(b.z, b.w);
        reinterpret_cast<uint4*>(dst)[j] = *reinterpret_cast<uint4*>(h);
    }
}

// ---------------- FP16 mma GEMM: C = A*B^T + bias ----------------------------
// CTA tile 128(M) x 64(N), 8 warps (4M x 2N), warp tile 32x32, BK=64 halves
// (=128B rows), 3-stage pipeline, mma m16n8k16, fp32 accum. 3 CTAs/SM.
// sel==0: A = fp32 inputs (LDG+cvt+STS inline), B=g_WiH, C=g_uh (fp16).
// sel==1: A = g_uh (cp.async),                  B=g_WoH, C=out (fp32).
constexpr int TM = 128, TN = 64, BKH = 64;    // BKH in halves
constexpr int KDIM = 1024;                    // halves
constexpr int NKT  = KDIM / BKH;              // 16 chunks
constexpr int NSTAGE = 3;
constexpr int STAGE_A   = TM * 128;           // 16384 B (A tile)
constexpr int STAGE_B   = TN * 128;           // 8192 B  (B tile)
constexpr int STAGE_TOT = STAGE_A + STAGE_B;  // 24576 B
constexpr int GEMM_SMEM = NSTAGE * STAGE_TOT; // 73728 B

__global__ __launch_bounds__(256, 3)
void gemm_f16_kernel(int sel, const float* __restrict__ Af32,
                     const float* __restrict__ bias, float* __restrict__ Cext)
{
    extern __shared__ char smem[];
    const uint32_t sb = smem_u32(smem);
    const int tid = threadIdx.x;
    const int warp = tid >> 5, lane = tid & 31;

    const __half* __restrict__ Ah = g_uh;               // sel==1 A source
    const __half* __restrict__ Bw = sel ? g_WoH : g_WiH;
    const int bm = blockIdx.y * TM;
    const int bn = blockIdx.x * TN;

    const int wm = (warp >> 1) * 32;      // warp M offset (0..96)
    const int wn = (warp & 1) * 32;       // warp N offset (0/32)

    // ---- staging: thread -> (row group, 16B chunk). 32 rows per pass. ----
    const int srow = tid >> 3;            // 0..31
    const int gcol = tid & 7;             // 16B chunk in 128B row
    uint32_t swA[4], swB[2];
    #pragma unroll
    for (int i = 0; i < 4; i++) {
        const int r = srow + 32 * i;
        swA[i] = (uint32_t)r * 128u + ((uint32_t)(gcol ^ (r & 7)) << 4);
    }
    #pragma unroll
    for (int i = 0; i < 2; i++) {
        const int r = srow + 32 * i;
        swB[i] = (uint32_t)r * 128u + ((uint32_t)(gcol ^ (r & 7)) << 4);
    }
    const __half* Arow  = Ah   + (size_t)(bm + srow) * KDIM + gcol * 8;  // sel==1
    const float*  Arow32= Af32 + (size_t)(bm + srow) * KDIM + gcol * 8;  // sel==0
    const __half* Brow  = Bw   + (size_t)(bn + srow) * KDIM + gcol * 8;

    // A staging for sel==0: LDG fp32 -> cvt -> STS.128 (same swizzled layout)
    auto stageA_f32 = [&](int stage, int k0) {
        const uint32_t ao = sb + stage * STAGE_TOT;
        #pragma unroll
        for (int i = 0; i < 4; i++) {
            const float* s = Arow32 + (size_t)(32 * i) * KDIM + k0;
            float4 a = *reinterpret_cast<const float4*>(s);
            float4 b = *reinterpret_cast<const float4*>(s + 4);
            __half2 h0 = __floats2half2_rn(a.x, a.y);
            __half2 h1 = __floats2half2_rn(a.z, a.w);
            __half2 h2 = __floats2half2_rn(b.x, b.y);
            __half2 h3 = __floats2half2_rn(b.z, b.w);
            sts128(ao + swA[i],
                   *reinterpret_cast<uint32_t*>(&h0), *reinterpret_cast<uint32_t*>(&h1),
                   *reinterpret_cast<uint32_t*>(&h2), *reinterpret_cast<uint32_t*>(&h3));
        }
    };

    // ---- ldmatrix per-lane invariants (x4, non-trans) ----
    const int lrA  = lane & 15;           // A row-in-16
    const int gsA  = lane >> 4;           // A k-chunk select (0/1)
    const int lrB  = ((lane & 16) >> 1) + (lane & 7);   // B row offset 0..15
    const int gsB  = (lane >> 3) & 1;     // B k-chunk select

    float acc[2][4][4];
    #pragma unroll
    for (int mt = 0; mt < 2; mt++)
        #pragma unroll
        for (int nt = 0; nt < 4; nt++)
            #pragma unroll
            for (int i = 0; i < 4; i++) acc[mt][nt][i] = 0.f;

    // ---- prologue: stage chunks 0,1 ----
    #pragma unroll
    for (int c = 0; c < NSTAGE - 1; c++) {
        const uint32_t ao = sb + c * STAGE_TOT;
        if (sel == 0) {
            stageA_f32(c, c * BKH);
        } else {
            #pragma unroll
            for (int i = 0; i < 4; i++)
                cp16(ao + swA[i], Arow + (size_t)(32 * i) * KDIM + c * BKH);
        }
        #pragma unroll
        for (int i = 0; i < 2; i++)
            cp16(ao + STAGE_A + swB[i], Brow + (size_t)(32 * i) * KDIM + c * BKH);
        cp_commit();
    }

    #pragma unroll 1
    for (int kt = 0; kt < NKT; kt++) {
        asm volatile("cp.async.wait_group 1;" ::: "memory");
        __syncthreads();

        if (kt + 2 < NKT) {
            const int stage = (kt + 2) % NSTAGE;
            const uint32_t ao = sb + stage * STAGE_TOT;
            const int k0 = (kt + 2) * BKH;
            if (sel == 0) {
                stageA_f32(stage, k0);
            } else {
                #pragma unroll
                for (int i = 0; i < 4; i++)
                    cp16(ao + swA[i], Arow + (size_t)(32 * i) * KDIM + k0);
            }
            #pragma unroll
            for (int i = 0; i < 2; i++)
                cp16(ao + STAGE_A + swB[i], Brow + (size_t)(32 * i) * KDIM + k0);
        }
        cp_commit();

        const uint32_t sA = sb + (kt % NSTAGE) * STAGE_TOT;
        const uint32_t sB = sA + STAGE_A;

        #pragma unroll
        for (int ks = 0; ks < 4; ks++) {          // 4 x k16 per 64-half chunk
            uint32_t afr[2][4], bfr[2][4];
            #pragma unroll
            for (int mt = 0; mt < 2; mt++) {
                const int r = wm + mt * 16 + lrA;
                const uint32_t g = (uint32_t)((ks * 2 + gsA) ^ (lrA & 7));
                ldsm4(afr[mt], sA + (uint32_t)r * 128u + (g << 4));
            }
            #pragma unroll
            for (int p = 0; p < 2; p++) {
                const int r = wn + p * 16 + lrB;
                const uint32_t g = (uint32_t)((ks * 2 + gsB) ^ (lrB & 7));
                ldsm4(bfr[p], sB + (uint32_t)r * 128u + (g << 4));
            }
            #pragma unroll
            for (int mt = 0; mt < 2; mt++)
                #pragma unroll
                for (int nt = 0; nt < 4; nt++)
                    mma_f16(acc[mt][nt], afr[mt], &bfr[nt >> 1][(nt & 1) * 2]);
        }
    }

    // ---- epilogue: add bias; write fp16 (sel=0 -> g_uh) or fp32 (sel=1) ----
    const int gid = lane >> 2, t4 = lane & 3;
    if (sel == 0) {
        #pragma unroll
        for (int mt = 0; mt < 2; mt++) {
            const int row = bm + wm + mt * 16 + gid;
            #pragma unroll
            for (int nt = 0; nt < 4; nt++) {
                const int col = bn + wn + nt * 8 + t4 * 2;
                const float b0 = bias[col], b1 = bias[col + 1];
                __half2 v0 = __floats2half2_rn(acc[mt][nt][0] + b0, acc[mt][nt][1] + b1);
                __half2 v1 = __floats2half2_rn(acc[mt][nt][2] + b0, acc[mt][nt][3] + b1);
                *reinterpret_cast<__half2*>(&g_uh[(size_t)row * 1024 + col]) = v0;
                *reinterpret_cast<__half2*>(&g_uh[(size_t)(row + 8) * 1024 + col]) = v1;
            }
        }
    } else {
        #pragma unroll
        for (int mt = 0; mt < 2; mt++) {
            const int row = bm + wm + mt * 16 + gid;
            #pragma unroll
            for (int nt = 0; nt < 4; nt++) {
                const int col = bn + wn + nt * 8 + t4 * 2;
                const float b0 = bias[col], b1 = bias[col + 1];
                float2 v0 = make_float2(acc[mt][nt][0] + b0, acc[mt][nt][1] + b1);
                float2 v1 = make_float2(acc[mt][nt][2] + b0, acc[mt][nt][3] + b1);
                *reinterpret_cast<float2*>(&Cext[(size_t)row * 1024 + col]) = v0;
                *reinterpret_cast<float2*>(&Cext[(size_t)(row + 8) * 1024 + col]) = v1;
            }
        }
    }
}

// ---------------- fused scan: agg -> carry -> apply, one kernel ---------------
__global__ __launch_bounds__(256)
void scan_fused_kernel(const float* __restrict__ plog)
{
    const int tid = threadIdx.x;

    // ---- phase 1: chunk aggregates -> g_v (2 u's per thread, half2) ----
    {
        const int g  = blockIdx.x * 256 + tid;
        const int u2 = g & (U_ / 2 - 1);
        const int c  = (g >> 9) & (NC - 1);
        const int b  = g >> 15;
        const int uu = u2 * 2;
        const float lam0 = expf(-expf(plog[uu]));
        const float lam1 = expf(-expf(plog[uu + 1]));
        const __half2* p = reinterpret_cast<const __half2*>(
            g_uh + (size_t)(b * L_ + c * CL) * U_) + u2;
        float h0 = 0.f, h1 = 0.f;
        #pragma unroll 8
        for (int t = 0; t < CL; t++) {
            float2 v = __half22float2(p[(size_t)t * (U_ / 2)]);
            h0 = fmaf(lam0, h0, v.x);
            h1 = fmaf(lam1, h1, v.y);
        }
        reinterpret_cast<float2*>(g_v + (size_t)(b * NC + c) * U_)[u2] =
            make_float2(h0, h1);
    }

    grid_bar(&g_cnt[0]);

    // ---- phase 2: exclusive scan of aggregates (one warp per (b,u)) ----
    {
        const int idx  = blockIdx.x * 256 + tid;
        const int lane = idx & 31;
        const int w    = idx >> 5;
        const int uu   = w & (U_ - 1);
        const int b    = w >> 10;
        const float nu   = expf(plog[uu]);
        const float lamC = expf(-(float)CL * nu);
        float* pv = g_v + (size_t)b * NC * U_ + uu;

        const float a0 = pv[(size_t)(2 * lane) * U_];
        const float a1 = pv[(size_t)(2 * lane + 1) * U_];
        float p = fmaf(lamC, a0, a1);
        const float lamC2 = lamC * lamC;

        float mult = lamC2;
        #pragma unroll
        for (int s = 1; s < 32; s <<= 1) {
            float other = __shfl_up_sync(0xffffffffu, p, s);
            if (lane >= s) p = fmaf(mult, other, p);
            mult = mult * mult;
        }

        const float Pprev = __shfl_up_sync(0xffffffffu, p, 1);
        const float E0 = (lane == 0) ? 0.f : Pprev;
        const float E1 = fmaf(lamC, E0, a0);
        pv[(size_t)(2 * lane) * U_]     = E0;
        pv[(size_t)(2 * lane + 1) * U_] = E1;
    }

    grid_bar(&g_cnt[1]);

    // ---- phase 3: redo local scan seeded with carry, * gamma, in place ----
    {
        const int g  = blockIdx.x * 256 + tid;
        const int u2 = g & (U_ / 2 - 1);
        const int c  = (g >> 9) & (NC - 1);
        const int b  = g >> 15;
        const int uu = u2 * 2;
        const float lam0 = expf(-expf(plog[uu]));
        const float lam1 = expf(-expf(plog[uu + 1]));
        const float gam0 = expf(plog[U_ + uu]);
        const float gam1 = expf(plog[U_ + uu + 1]);
        float2 h = reinterpret_cast<const float2*>(
            g_v + (size_t)(b * NC + c) * U_)[u2];
        __half2* p = reinterpret_cast<__half2*>(
            g_uh + (size_t)(b * L_ + c * CL) * U_) + u2;
        #pragma unroll 8
        for (int t = 0; t < CL; t++) {
            float2 v = __half22float2(p[(size_t)t * (U_ / 2)]);
            h.x = fmaf(lam0, h.x, v.x);
            h.y = fmaf(lam1, h.y, v.y);
            p[(size_t)t * (U_ / 2)] = __floats2half2_rn(h.x * gam0, h.y * gam1);
        }
    }
}

// ---------------- launch ------------------------------------------------------
extern "C" void kernel_launch(void* const* d_in, const int* in_sizes, int n_in,
                              void* d_out, int out_size)
{
    const float* inputs = (const float*)d_in[0];
    const float* Wi     = (const float*)d_in[1];
    const float* bi     = (const float*)d_in[2];
    const float* Wo     = (const float*)d_in[3];
    const float* bo     = (const float*)d_in[4];
    const float* plog   = (const float*)d_in[5];
    float* out = (float*)d_out;

    cudaFuncSetAttribute(gemm_f16_kernel,
                         cudaFuncAttributeMaxDynamicSharedMemorySize, GEMM_SMEM);

    // weights fp16 conversion (also resets the scan grid-barrier counters)
    cvt_w_kernel<<<512, 256>>>((const float4*)Wi, (const float4*)Wo);

    // GEMM1: u = inputs * Wi^T + bi   -> g_uh (fp16); inputs converted inline
    gemm_f16_kernel<<<dim3(U_ / TN, M_ / TM), 256, GEMM_SMEM>>>(0, inputs, bi, nullptr);

    // fused scan (agg -> carry -> apply), in place on g_uh
    scan_fused_kernel<<<(B_ * NC * U_ / 2) / 256, 256>>>(plog);

    // GEMM2: out = x * Wo^T + bo
    gemm_f16_kernel<<<dim3(H_ / TN, M_ / TM), 256, GEMM_SMEM>>>(1, nullptr, bo, out);
}

// round 15
// speedup vs baseline: 1.3676x; 1.3676x over previous
#include <cuda_runtime.h>
#include <cuda_fp16.h>
#include <cstdint>

// Problem constants
#define B_  4
#define L_  4096
#define H_  1024
#define U_  1024
#define M_  (B_*L_)          // 16384 rows

constexpr int CL = 64;            // scan chunk length
constexpr int NC = L_ / CL;       // 64 chunks per sequence

// ---------------- scratch (device globals; no allocation allowed) -------------
__device__ __half g_inH[(size_t)M_ * H_];   // fp16 inputs          (32 MB)
__device__ __half g_WiH[(size_t)U_ * H_];   // fp16 Wi              (2 MB)
__device__ __half g_WoH[(size_t)H_ * U_];   // fp16 Wo              (2 MB)
__device__ __half g_uh [(size_t)M_ * U_];   // fp16 u, then scanned x (32 MB)
__device__ float  g_v  [(size_t)B_ * NC * U_]; // chunk carries      (1 MB)
__device__ unsigned g_cnt[2];               // grid-barrier counters (reset by cvt)

// ---------------- helpers ----------------------------------------------------
__device__ __forceinline__ uint32_t smem_u32(const void* p) {
    uint32_t a;
    asm("{ .reg .u64 t; cvta.to.shared.u64 t, %1; cvt.u32.u64 %0, t; }"
        : "=r"(a) : "l"(p));
    return a;
}

__device__ __forceinline__ void cp16(uint32_t saddr, const void* g) {
    asm volatile("cp.async.cg.shared.global [%0], [%1], 16;" :: "r"(saddr), "l"(g));
}
__device__ __forceinline__ void cp_commit() {
    asm volatile("cp.async.commit_group;" ::: "memory");
}

// ldmatrix x4: 4 matrices of 8 rows x 16B (8 halves).
__device__ __forceinline__ void ldsm4(uint32_t* r, uint32_t addr) {
    asm volatile("ldmatrix.sync.aligned.m8n8.x4.shared.b16 {%0,%1,%2,%3}, [%4];"
                 : "=r"(r[0]), "=r"(r[1]), "=r"(r[2]), "=r"(r[3]) : "r"(addr));
}

// fp32-accumulate MMA
__device__ __forceinline__ void mma_f16(float* d, const uint32_t* a, const uint32_t* b) {
    asm volatile(
        "mma.sync.aligned.m16n8k16.row.col.f32.f16.f16.f32 "
        "{%0,%1,%2,%3}, {%4,%5,%6,%7}, {%8,%9}, {%0,%1,%2,%3};\n"
        : "+f"(d[0]), "+f"(d[1]), "+f"(d[2]), "+f"(d[3])
        : "r"(a[0]), "r"(a[1]), "r"(a[2]), "r"(a[3]),
          "r"(b[0]), "r"(b[1]));
}

// device-wide spin barrier (all gridDim.x blocks must be co-resident)
__device__ __forceinline__ void grid_bar(unsigned* cnt) {
    __syncthreads();
    if (threadIdx.x == 0) {
        __threadfence();
        atomicAdd(cnt, 1u);
        while (*(volatile unsigned*)cnt < gridDim.x) { __nanosleep(32); }
    }
    __syncthreads();
    __threadfence();
}

// ---------------- fused fp16 conversion (inputs + Wi + Wo) --------------------
__global__ void cvt_all_kernel(const float4* __restrict__ in,
                               const float4* __restrict__ wi,
                               const float4* __restrict__ wo)
{
    if (blockIdx.x == 0 && threadIdx.x == 0) {   // reset scan grid-barriers
        g_cnt[0] = 0;
        g_cnt[1] = 0;
    }
    const size_t n_in = (size_t)M_ * H_ / 8;    // uint4 (8-half) chunks
    const size_t n_w  = (size_t)U_ * H_ / 8;
    const size_t n_tot = n_in + 2 * n_w;
    size_t i = (size_t)blockIdx.x * blockDim.x + threadIdx.x;
    const size_t stride = (size_t)gridDim.x * blockDim.x;
    for (; i < n_tot; i += stride) {
        const float4* src;
        __half* dst;
        size_t j;
        if (i < n_in)            { src = in; dst = g_inH; j = i; }
        else if (i < n_in + n_w) { src = wi; dst = g_WiH; j = i - n_in; }
        else                     { src = wo; dst = g_WoH; j = i - n_in - n_w; }
        float4 a = src[2 * j], b = src[2 * j + 1];
        __half2 h[4];
        h[0] = __floats2half2_rn(a.x, a.y);
        h[1] = __floats2half2_rn(a.z, a.w);
        h[2] = __floats2half2_rn(b.x, b.y);
        h[3] = __floats2half2_rn(b.z, b.w);
        reinterpret_cast<uint4*>(dst)[j] = *reinterpret_cast<uint4*>(h);
    }
}

// ---------------- FP16 mma GEMM: C = A*B^T + bias ----------------------------
// CTA tile 128(M) x 64(N), 8 warps (4M x 2N), warp tile 32x32, BK=64 halves
// (=128B rows), 3-stage cp.async, mma m16n8k16, fp32 accum. 3 CTAs/SM.
// sel==0: A=g_inH, B=g_WiH, C=g_uh (fp16).  sel==1: A=g_uh, B=g_WoH, C=out(fp32).
constexpr int TM = 128, TN = 64, BKH = 64;    // BKH in halves
constexpr int KDIM = 1024;                    // halves
constexpr int NKT  = KDIM / BKH;              // 16 chunks
constexpr int NSTAGE = 3;
constexpr int STAGE_A   = TM * 128;           // 16384 B (A tile)
constexpr int STAGE_B   = TN * 128;           // 8192 B  (B tile)
constexpr int STAGE_TOT = STAGE_A + STAGE_B;  // 24576 B
constexpr int GEMM_SMEM = NSTAGE * STAGE_TOT; // 73728 B

__global__ __launch_bounds__(256, 3)
void gemm_f16_kernel(int sel, const float* __restrict__ bias, float* __restrict__ Cext)
{
    extern __shared__ char smem[];
    const uint32_t sb = smem_u32(smem);
    const int tid = threadIdx.x;
    const int warp = tid >> 5, lane = tid & 31;

    const __half* __restrict__ A  = sel ? g_uh  : g_inH;
    const __half* __restrict__ Bw = sel ? g_WoH : g_WiH;
    const int bm = blockIdx.y * TM;
    const int bn = blockIdx.x * TN;

    const int wm = (warp >> 1) * 32;      // warp M offset (0..96)
    const int wn = (warp & 1) * 32;       // warp N offset (0/32)

    // ---- staging: thread -> (row group, 16B chunk). 32 rows per pass. ----
    const int srow = tid >> 3;            // 0..31
    const int gcol = tid & 7;             // 16B chunk in 128B row
    uint32_t swA[4], swB[2];
    #pragma unroll
    for (int i = 0; i < 4; i++) {
        const int r = srow + 32 * i;
        swA[i] = (uint32_t)r * 128u + ((uint32_t)(gcol ^ (r & 7)) << 4);
    }
    #pragma unroll
    for (int i = 0; i < 2; i++) {
        const int r = srow + 32 * i;
        swB[i] = (uint32_t)r * 128u + ((uint32_t)(gcol ^ (r & 7)) << 4);
    }
    const __half* Arow = A  + (size_t)(bm + srow) * KDIM + gcol * 8;
    const __half* Brow = Bw + (size_t)(bn + srow) * KDIM + gcol * 8;

    // ---- ldmatrix per-lane invariants (x4, non-trans) ----
    const int lrA  = lane & 15;           // A row-in-16
    const int gsA  = lane >> 4;           // A k-chunk select (0/1)
    const int lrB  = ((lane & 16) >> 1) + (lane & 7);   // B row offset 0..15
    const int gsB  = (lane >> 3) & 1;     // B k-chunk select

    float acc[2][4][4];
    #pragma unroll
    for (int mt = 0; mt < 2; mt++)
        #pragma unroll
        for (int nt = 0; nt < 4; nt++)
            #pragma unroll
            for (int i = 0; i < 4; i++) acc[mt][nt][i] = 0.f;

    // ---- prologue: stage chunks 0,1 ----
    #pragma unroll
    for (int c = 0; c < NSTAGE - 1; c++) {
        const uint32_t ao = sb + c * STAGE_TOT;
        #pragma unroll
        for (int i = 0; i < 4; i++)
            cp16(ao + swA[i], Arow + (size_t)(32 * i) * KDIM + c * BKH);
        #pragma unroll
        for (int i = 0; i < 2; i++)
            cp16(ao + STAGE_A + swB[i], Brow + (size_t)(32 * i) * KDIM + c * BKH);
        cp_commit();
    }

    #pragma unroll 1
    for (int kt = 0; kt < NKT; kt++) {
        asm volatile("cp.async.wait_group 1;" ::: "memory");
        __syncthreads();

        if (kt + 2 < NKT) {
            const uint32_t ao = sb + ((kt + 2) % NSTAGE) * STAGE_TOT;
            const int k0 = (kt + 2) * BKH;
            #pragma unroll
            for (int i = 0; i < 4; i++)
                cp16(ao + swA[i], Arow + (size_t)(32 * i) * KDIM + k0);
            #pragma unroll
            for (int i = 0; i < 2; i++)
                cp16(ao + STAGE_A + swB[i], Brow + (size_t)(32 * i) * KDIM + k0);
        }
        cp_commit();

        const uint32_t sA = sb + (kt % NSTAGE) * STAGE_TOT;
        const uint32_t sB = sA + STAGE_A;

        #pragma unroll
        for (int ks = 0; ks < 4; ks++) {          // 4 x k16 per 64-half chunk
            uint32_t afr[2][4], bfr[2][4];
            #pragma unroll
            for (int mt = 0; mt < 2; mt++) {
                const int r = wm + mt * 16 + lrA;
                const uint32_t g = (uint32_t)((ks * 2 + gsA) ^ (lrA & 7));
                ldsm4(afr[mt], sA + (uint32_t)r * 128u + (g << 4));
            }
            #pragma unroll
            for (int p = 0; p < 2; p++) {
                const int r = wn + p * 16 + lrB;
                const uint32_t g = (uint32_t)((ks * 2 + gsB) ^ (lrB & 7));
                ldsm4(bfr[p], sB + (uint32_t)r * 128u + (g << 4));
            }
            #pragma unroll
            for (int mt = 0; mt < 2; mt++)
                #pragma unroll
                for (int nt = 0; nt < 4; nt++)
                    mma_f16(acc[mt][nt], afr[mt], &bfr[nt >> 1][(nt & 1) * 2]);
        }
    }

    // ---- epilogue: add bias; write fp16 (sel=0 -> g_uh) or fp32 (sel=1) ----
    const int gid = lane >> 2, t4 = lane & 3;
    if (sel == 0) {
        #pragma unroll
        for (int mt = 0; mt < 2; mt++) {
            const int row = bm + wm + mt * 16 + gid;
            #pragma unroll
            for (int nt = 0; nt < 4; nt++) {
                const int col = bn + wn + nt * 8 + t4 * 2;
                const float b0 = bias[col], b1 = bias[col + 1];
                __half2 v0 = __floats2half2_rn(acc[mt][nt][0] + b0, acc[mt][nt][1] + b1);
                __half2 v1 = __floats2half2_rn(acc[mt][nt][2] + b0, acc[mt][nt][3] + b1);
                *reinterpret_cast<__half2*>(&g_uh[(size_t)row * 1024 + col]) = v0;
                *reinterpret_cast<__half2*>(&g_uh[(size_t)(row + 8) * 1024 + col]) = v1;
            }
        }
    } else {
        #pragma unroll
        for (int mt = 0; mt < 2; mt++) {
            const int row = bm + wm + mt * 16 + gid;
            #pragma unroll
            for (int nt = 0; nt < 4; nt++) {
                const int col = bn + wn + nt * 8 + t4 * 2;
                const float b0 = bias[col], b1 = bias[col + 1];
                float2 v0 = make_float2(acc[mt][nt][0] + b0, acc[mt][nt][1] + b1);
                float2 v1 = make_float2(acc[mt][nt][2] + b0, acc[mt][nt][3] + b1);
                *reinterpret_cast<float2*>(&Cext[(size_t)row * 1024 + col]) = v0;
                *reinterpret_cast<float2*>(&Cext[(size_t)(row + 8) * 1024 + col]) = v1;
            }
        }
    }
}

// ---------------- fused scan: agg -> carry -> apply, one kernel ---------------
// 128 blocks x 256 threads. Phases 1/3: 8 channels per thread (16B loads).
// Phase 2: one warp per (b,u), looping 4x. fp32 math, fp16 storage.
__global__ __launch_bounds__(256)
void scan_fused_kernel(const float* __restrict__ plog)
{
    const int tid = threadIdx.x;
    const int g   = blockIdx.x * 256 + tid;      // 0 .. 32767
    const int u8  = g & 127;                     // 8-half group in u
    const int c   = (g >> 7) & (NC - 1);
    const int b   = g >> 13;
    const int uu  = u8 * 8;

    float lam[8];
    #pragma unroll
    for (int j = 0; j < 8; j++) lam[j] = expf(-expf(plog[uu + j]));

    // ---- phase 1: chunk aggregates -> g_v ----
    {
        const float4* p = reinterpret_cast<const float4*>(
            g_uh + (size_t)(b * L_ + c * CL) * U_) + u8;
        float h[8];
        #pragma unroll
        for (int j = 0; j < 8; j++) h[j] = 0.f;
        #pragma unroll 4
        for (int t = 0; t < CL; t++) {
            float4 v4 = p[(size_t)t * (U_ / 8)];
            const __half2* hh = reinterpret_cast<const __half2*>(&v4);
            #pragma unroll
            for (int j = 0; j < 4; j++) {
                float2 f = __half22float2(hh[j]);
                h[2 * j]     = fmaf(lam[2 * j],     h[2 * j],     f.x);
                h[2 * j + 1] = fmaf(lam[2 * j + 1], h[2 * j + 1], f.y);
            }
        }
        float4* ov = reinterpret_cast<float4*>(
            g_v + (size_t)(b * NC + c) * U_) + u8 * 2;
        ov[0] = make_float4(h[0], h[1], h[2], h[3]);
        ov[1] = make_float4(h[4], h[5], h[6], h[7]);
    }

    grid_bar(&g_cnt[0]);

    // ---- phase 2: exclusive scan of aggregates (one warp per (b,u), x4) ----
    {
        const int lane = tid & 31;
        const int warp0 = (blockIdx.x * 256 + tid) >> 5;   // 0..1023
        #pragma unroll 1
        for (int it = 0; it < 4; it++) {
            const int w  = warp0 + it * 1024;              // 0 .. B_*U_-1
            const int uw = w & (U_ - 1);
            const int bw = w >> 10;
            const float nu   = expf(plog[uw]);
            const float lamC = expf(-(float)CL * nu);
            float* pv = g_v + (size_t)bw * NC * U_ + uw;

            const float a0 = pv[(size_t)(2 * lane) * U_];
            const float a1 = pv[(size_t)(2 * lane + 1) * U_];
            float p = fmaf(lamC, a0, a1);
            const float lamC2 = lamC * lamC;

            float mult = lamC2;
            #pragma unroll
            for (int s = 1; s < 32; s <<= 1) {
                float other = __shfl_up_sync(0xffffffffu, p, s);
                if (lane >= s) p = fmaf(mult, other, p);
                mult = mult * mult;
            }

            const float Pprev = __shfl_up_sync(0xffffffffu, p, 1);
            const float E0 = (lane == 0) ? 0.f : Pprev;
            const float E1 = fmaf(lamC, E0, a0);
            pv[(size_t)(2 * lane) * U_]     = E0;
            pv[(size_t)(2 * lane + 1) * U_] = E1;
        }
    }

    grid_bar(&g_cnt[1]);

    // ---- phase 3: redo local scan seeded with carry, * gamma, in place ----
    {
        float gam[8], h[8];
        #pragma unroll
        for (int j = 0; j < 8; j++) gam[j] = expf(plog[U_ + uu + j]);
        const float4* sv = reinterpret_cast<const float4*>(
            g_v + (size_t)(b * NC + c) * U_) + u8 * 2;
        float4 s0 = sv[0], s1 = sv[1];
        h[0] = s0.x; h[1] = s0.y; h[2] = s0.z; h[3] = s0.w;
        h[4] = s1.x; h[5] = s1.y; h[6] = s1.z; h[7] = s1.w;

        float4* p = reinterpret_cast<float4*>(
            g_uh + (size_t)(b * L_ + c * CL) * U_) + u8;
        #pragma unroll 4
        for (int t = 0; t < CL; t++) {
            float4 v4 = p[(size_t)t * (U_ / 8)];
            const __half2* hh = reinterpret_cast<const __half2*>(&v4);
            __half2 o[4];
            #pragma unroll
            for (int j = 0; j < 4; j++) {
                float2 f = __half22float2(hh[j]);
                h[2 * j]     = fmaf(lam[2 * j],     h[2 * j],     f.x);
                h[2 * j + 1] = fmaf(lam[2 * j + 1], h[2 * j + 1], f.y);
                o[j] = __floats2half2_rn(h[2 * j] * gam[2 * j],
                                         h[2 * j + 1] * gam[2 * j + 1]);
            }
            p[(size_t)t * (U_ / 8)] = *reinterpret_cast<float4*>(o);
        }
    }
}

// ---------------- launch ------------------------------------------------------
extern "C" void kernel_launch(void* const* d_in, const int* in_sizes, int n_in,
                              void* d_out, int out_size)
{
    const float* inputs = (const float*)d_in[0];
    const float* Wi     = (const float*)d_in[1];
    const float* bi     = (const float*)d_in[2];
    const float* Wo     = (const float*)d_in[3];
    const float* bo     = (const float*)d_in[4];
    const float* plog   = (const float*)d_in[5];
    float* out = (float*)d_out;

    cudaFuncSetAttribute(gemm_f16_kernel,
                         cudaFuncAttributeMaxDynamicSharedMemorySize, GEMM_SMEM);

    // fp16 conversion (also resets the scan grid-barrier counters)
    cvt_all_kernel<<<2048, 256>>>((const float4*)inputs,
                                  (const float4*)Wi,
                                  (const float4*)Wo);

    // GEMM1: u = inputs * Wi^T + bi   -> g_uh (fp16)
    gemm_f16_kernel<<<dim3(U_ / TN, M_ / TM), 256, GEMM_SMEM>>>(0, bi, nullptr);

    // fused scan (agg -> carry -> apply), in place on g_uh
    scan_fused_kernel<<<128, 256>>>(plog);

    // GEMM2: out = x * Wo^T + bo
    gemm_f16_kernel<<<dim3(H_ / TN, M_ / TM), 256, GEMM_SMEM>>>(1, bo, out);
}

// round 16
// speedup vs baseline: 1.4077x; 1.0293x over previous
#include <cuda_runtime.h>
#include <cuda_fp16.h>
#include <cstdint>

// Problem constants
#define B_  4
#define L_  4096
#define H_  1024
#define U_  1024
#define M_  (B_*L_)          // 16384 rows

constexpr int CL = 64;            // scan chunk length
constexpr int NC = L_ / CL;       // 64 chunks per sequence

// ---------------- scratch (device globals; no allocation allowed) -------------
__device__ __half g_inH[(size_t)M_ * H_];   // fp16 inputs          (32 MB)
__device__ __half g_WiH[(size_t)U_ * H_];   // fp16 Wi              (2 MB)
__device__ __half g_WoH[(size_t)H_ * U_];   // fp16 Wo              (2 MB)
__device__ __half g_uh [(size_t)M_ * U_];   // fp16 u, then scanned x (32 MB)
__device__ float  g_v  [(size_t)B_ * NC * U_]; // chunk carries      (1 MB)
__device__ unsigned g_cnt[2];               // grid-barrier counters (reset by cvt)

// ---------------- helpers ----------------------------------------------------
__device__ __forceinline__ uint32_t smem_u32(const void* p) {
    uint32_t a;
    asm("{ .reg .u64 t; cvta.to.shared.u64 t, %1; cvt.u32.u64 %0, t; }"
        : "=r"(a) : "l"(p));
    return a;
}

__device__ __forceinline__ void cp16(uint32_t saddr, const void* g) {
    asm volatile("cp.async.cg.shared.global [%0], [%1], 16;" :: "r"(saddr), "l"(g));
}
__device__ __forceinline__ void cp_commit() {
    asm volatile("cp.async.commit_group;" ::: "memory");
}

// ldmatrix x4: 4 matrices of 8 rows x 16B (8 halves).
__device__ __forceinline__ void ldsm4(uint32_t* r, uint32_t addr) {
    asm volatile("ldmatrix.sync.aligned.m8n8.x4.shared.b16 {%0,%1,%2,%3}, [%4];"
                 : "=r"(r[0]), "=r"(r[1]), "=r"(r[2]), "=r"(r[3]) : "r"(addr));
}

// fp32-accumulate MMA
__device__ __forceinline__ void mma_f16(float* d, const uint32_t* a, const uint32_t* b) {
    asm volatile(
        "mma.sync.aligned.m16n8k16.row.col.f32.f16.f16.f32 "
        "{%0,%1,%2,%3}, {%4,%5,%6,%7}, {%8,%9}, {%0,%1,%2,%3};\n"
        : "+f"(d[0]), "+f"(d[1]), "+f"(d[2]), "+f"(d[3])
        : "r"(a[0]), "r"(a[1]), "r"(a[2]), "r"(a[3]),
          "r"(b[0]), "r"(b[1]));
}

// device-wide spin barrier (all gridDim.x blocks must be co-resident)
__device__ __forceinline__ void grid_bar(unsigned* cnt) {
    __syncthreads();
    if (threadIdx.x == 0) {
        __threadfence();
        atomicAdd(cnt, 1u);
        while (*(volatile unsigned*)cnt < gridDim.x) { __nanosleep(32); }
    }
    __syncthreads();
    __threadfence();
}

// ---------------- fused fp16 conversion (inputs + Wi + Wo) --------------------
__global__ void cvt_all_kernel(const float4* __restrict__ in,
                               const float4* __restrict__ wi,
                               const float4* __restrict__ wo)
{
    if (blockIdx.x == 0 && threadIdx.x == 0) {   // reset scan grid-barriers
        g_cnt[0] = 0;
        g_cnt[1] = 0;
    }
    const size_t n_in = (size_t)M_ * H_ / 8;    // uint4 (8-half) chunks
    const size_t n_w  = (size_t)U_ * H_ / 8;
    const size_t n_tot = n_in + 2 * n_w;
    size_t i = (size_t)blockIdx.x * blockDim.x + threadIdx.x;
    const size_t stride = (size_t)gridDim.x * blockDim.x;
    for (; i < n_tot; i += stride) {
        const float4* src;
        __half* dst;
        size_t j;
        if (i < n_in)            { src = in; dst = g_inH; j = i; }
        else if (i < n_in + n_w) { src = wi; dst = g_WiH; j = i - n_in; }
        else                     { src = wo; dst = g_WoH; j = i - n_in - n_w; }
        float4 a = src[2 * j], b = src[2 * j + 1];
        __half2 h[4];
        h[0] = __floats2half2_rn(a.x, a.y);
        h[1] = __floats2half2_rn(a.z, a.w);
        h[2] = __floats2half2_rn(b.x, b.y);
        h[3] = __floats2half2_rn(b.z, b.w);
        reinterpret_cast<uint4*>(dst)[j] = *reinterpret_cast<uint4*>(h);
    }
}

// ---------------- FP16 mma GEMM: C = A*B^T + bias ----------------------------
// CTA tile 128(M) x 64(N), 8 warps (4M x 2N), warp tile 32x32, BK=64 halves
// (=128B rows), 3-stage cp.async, mma m16n8k16, fp32 accum. 3 CTAs/SM.
// sel==0: A=g_inH, B=g_WiH, C=g_uh (fp16).  sel==1: A=g_uh, B=g_WoH, C=out(fp32).
constexpr int TM = 128, TN = 64, BKH = 64;    // BKH in halves
constexpr int KDIM = 1024;                    // halves
constexpr int NKT  = KDIM / BKH;              // 16 chunks
constexpr int NSTAGE = 3;
constexpr int STAGE_A   = TM * 128;           // 16384 B (A tile)
constexpr int STAGE_B   = TN * 128;           // 8192 B  (B tile)
constexpr int STAGE_TOT = STAGE_A + STAGE_B;  // 24576 B
constexpr int GEMM_SMEM = NSTAGE * STAGE_TOT; // 73728 B

__global__ __launch_bounds__(256, 3)
void gemm_f16_kernel(int sel, const float* __restrict__ bias, float* __restrict__ Cext)
{
    extern __shared__ char smem[];
    const uint32_t sb = smem_u32(smem);
    const int tid = threadIdx.x;
    const int warp = tid >> 5, lane = tid & 31;

    const __half* __restrict__ A  = sel ? g_uh  : g_inH;
    const __half* __restrict__ Bw = sel ? g_WoH : g_WiH;
    const int bm = blockIdx.y * TM;
    const int bn = blockIdx.x * TN;

    const int wm = (warp >> 1) * 32;      // warp M offset (0..96)
    const int wn = (warp & 1) * 32;       // warp N offset (0/32)

    // ---- staging: thread -> (row group, 16B chunk). 32 rows per pass. ----
    const int srow = tid >> 3;            // 0..31
    const int gcol = tid & 7;             // 16B chunk in 128B row
    uint32_t swA[4], swB[2];
    #pragma unroll
    for (int i = 0; i < 4; i++) {
        const int r = srow + 32 * i;
        swA[i] = (uint32_t)r * 128u + ((uint32_t)(gcol ^ (r & 7)) << 4);
    }
    #pragma unroll
    for (int i = 0; i < 2; i++) {
        const int r = srow + 32 * i;
        swB[i] = (uint32_t)r * 128u + ((uint32_t)(gcol ^ (r & 7)) << 4);
    }
    const __half* Arow = A  + (size_t)(bm + srow) * KDIM + gcol * 8;
    const __half* Brow = Bw + (size_t)(bn + srow) * KDIM + gcol * 8;

    // ---- ldmatrix per-lane invariants (x4, non-trans) ----
    const int lrA  = lane & 15;           // A row-in-16
    const int gsA  = lane >> 4;           // A k-chunk select (0/1)
    const int lrB  = ((lane & 16) >> 1) + (lane & 7);   // B row offset 0..15
    const int gsB  = (lane >> 3) & 1;     // B k-chunk select

    float acc[2][4][4];
    #pragma unroll
    for (int mt = 0; mt < 2; mt++)
        #pragma unroll
        for (int nt = 0; nt < 4; nt++)
            #pragma unroll
            for (int i = 0; i < 4; i++) acc[mt][nt][i] = 0.f;

    // ---- prologue: stage chunks 0,1 ----
    #pragma unroll
    for (int c = 0; c < NSTAGE - 1; c++) {
        const uint32_t ao = sb + c * STAGE_TOT;
        #pragma unroll
        for (int i = 0; i < 4; i++)
            cp16(ao + swA[i], Arow + (size_t)(32 * i) * KDIM + c * BKH);
        #pragma unroll
        for (int i = 0; i < 2; i++)
            cp16(ao + STAGE_A + swB[i], Brow + (size_t)(32 * i) * KDIM + c * BKH);
        cp_commit();
    }

    #pragma unroll 1
    for (int kt = 0; kt < NKT; kt++) {
        asm volatile("cp.async.wait_group 1;" ::: "memory");
        __syncthreads();

        if (kt + 2 < NKT) {
            const uint32_t ao = sb + ((kt + 2) % NSTAGE) * STAGE_TOT;
            const int k0 = (kt + 2) * BKH;
            #pragma unroll
            for (int i = 0; i < 4; i++)
                cp16(ao + swA[i], Arow + (size_t)(32 * i) * KDIM + k0);
            #pragma unroll
            for (int i = 0; i < 2; i++)
                cp16(ao + STAGE_A + swB[i], Brow + (size_t)(32 * i) * KDIM + k0);
        }
        cp_commit();

        const uint32_t sA = sb + (kt % NSTAGE) * STAGE_TOT;
        const uint32_t sB = sA + STAGE_A;

        #pragma unroll
        for (int ks = 0; ks < 4; ks++) {          // 4 x k16 per 64-half chunk
            uint32_t afr[2][4], bfr[2][4];
            #pragma unroll
            for (int mt = 0; mt < 2; mt++) {
                const int r = wm + mt * 16 + lrA;
                const uint32_t g = (uint32_t)((ks * 2 + gsA) ^ (lrA & 7));
                ldsm4(afr[mt], sA + (uint32_t)r * 128u + (g << 4));
            }
            #pragma unroll
            for (int p = 0; p < 2; p++) {
                const int r = wn + p * 16 + lrB;
                const uint32_t g = (uint32_t)((ks * 2 + gsB) ^ (lrB & 7));
                ldsm4(bfr[p], sB + (uint32_t)r * 128u + (g << 4));
            }
            #pragma unroll
            for (int mt = 0; mt < 2; mt++)
                #pragma unroll
                for (int nt = 0; nt < 4; nt++)
                    mma_f16(acc[mt][nt], afr[mt], &bfr[nt >> 1][(nt & 1) * 2]);
        }
    }

    // ---- epilogue: add bias; write fp16 (sel=0 -> g_uh) or fp32 (sel=1) ----
    const int gid = lane >> 2, t4 = lane & 3;
    if (sel == 0) {
        #pragma unroll
        for (int mt = 0; mt < 2; mt++) {
            const int row = bm + wm + mt * 16 + gid;
            #pragma unroll
            for (int nt = 0; nt < 4; nt++) {
                const int col = bn + wn + nt * 8 + t4 * 2;
                const float b0 = bias[col], b1 = bias[col + 1];
                __half2 v0 = __floats2half2_rn(acc[mt][nt][0] + b0, acc[mt][nt][1] + b1);
                __half2 v1 = __floats2half2_rn(acc[mt][nt][2] + b0, acc[mt][nt][3] + b1);
                *reinterpret_cast<__half2*>(&g_uh[(size_t)row * 1024 + col]) = v0;
                *reinterpret_cast<__half2*>(&g_uh[(size_t)(row + 8) * 1024 + col]) = v1;
            }
        }
    } else {
        #pragma unroll
        for (int mt = 0; mt < 2; mt++) {
            const int row = bm + wm + mt * 16 + gid;
            #pragma unroll
            for (int nt = 0; nt < 4; nt++) {
                const int col = bn + wn + nt * 8 + t4 * 2;
                const float b0 = bias[col], b1 = bias[col + 1];
                float2 v0 = make_float2(acc[mt][nt][0] + b0, acc[mt][nt][1] + b1);
                float2 v1 = make_float2(acc[mt][nt][2] + b0, acc[mt][nt][3] + b1);
                *reinterpret_cast<float2*>(&Cext[(size_t)row * 1024 + col]) = v0;
                *reinterpret_cast<float2*>(&Cext[(size_t)(row + 8) * 1024 + col]) = v1;
            }
        }
    }
}

// ---------------- fused scan: agg -> carry -> apply, one kernel ---------------
// 256 blocks x 256 threads. Phases 1/3: 4 channels per thread (8B loads).
// Phase 2: one warp per (b,u), looping 2x. fp32 math, fp16 storage.
__global__ __launch_bounds__(256)
void scan_fused_kernel(const float* __restrict__ plog)
{
    const int tid = threadIdx.x;
    const int g   = blockIdx.x * 256 + tid;      // 0 .. 65535
    const int u4  = g & 255;                     // 4-half group in u
    const int c   = (g >> 8) & (NC - 1);
    const int b   = g >> 14;
    const int uu  = u4 * 4;

    float lam[4];
    #pragma unroll
    for (int j = 0; j < 4; j++) lam[j] = expf(-expf(plog[uu + j]));

    // ---- phase 1: chunk aggregates -> g_v ----
    {
        const uint2* p = reinterpret_cast<const uint2*>(
            g_uh + (size_t)(b * L_ + c * CL) * U_) + u4;
        float h[4];
        #pragma unroll
        for (int j = 0; j < 4; j++) h[j] = 0.f;
        #pragma unroll 8
        for (int t = 0; t < CL; t++) {
            uint2 v2 = p[(size_t)t * (U_ / 4)];
            const __half2* hh = reinterpret_cast<const __half2*>(&v2);
            #pragma unroll
            for (int j = 0; j < 2; j++) {
                float2 f = __half22float2(hh[j]);
                h[2 * j]     = fmaf(lam[2 * j],     h[2 * j],     f.x);
                h[2 * j + 1] = fmaf(lam[2 * j + 1], h[2 * j + 1], f.y);
            }
        }
        reinterpret_cast<float4*>(g_v + (size_t)(b * NC + c) * U_)[u4] =
            make_float4(h[0], h[1], h[2], h[3]);
    }

    grid_bar(&g_cnt[0]);

    // ---- phase 2: exclusive scan of aggregates (one warp per (b,u), x2) ----
    {
        const int lane = tid & 31;
        const int warp0 = (blockIdx.x * 256 + tid) >> 5;   // 0..2047
        #pragma unroll 1
        for (int it = 0; it < 2; it++) {
            const int w  = warp0 + it * 2048;              // 0 .. B_*U_-1
            const int uw = w & (U_ - 1);
            const int bw = w >> 10;
            const float nu   = expf(plog[uw]);
            const float lamC = expf(-(float)CL * nu);
            float* pv = g_v + (size_t)bw * NC * U_ + uw;

            const float a0 = pv[(size_t)(2 * lane) * U_];
            const float a1 = pv[(size_t)(2 * lane + 1) * U_];
            float p = fmaf(lamC, a0, a1);
            const float lamC2 = lamC * lamC;

            float mult = lamC2;
            #pragma unroll
            for (int s = 1; s < 32; s <<= 1) {
                float other = __shfl_up_sync(0xffffffffu, p, s);
                if (lane >= s) p = fmaf(mult, other, p);
                mult = mult * mult;
            }

            const float Pprev = __shfl_up_sync(0xffffffffu, p, 1);
            const float E0 = (lane == 0) ? 0.f : Pprev;
            const float E1 = fmaf(lamC, E0, a0);
            pv[(size_t)(2 * lane) * U_]     = E0;
            pv[(size_t)(2 * lane + 1) * U_] = E1;
        }
    }

    grid_bar(&g_cnt[1]);

    // ---- phase 3: redo local scan seeded with carry, * gamma, in place ----
    {
        float gam[4], h[4];
        #pragma unroll
        for (int j = 0; j < 4; j++) gam[j] = expf(plog[U_ + uu + j]);
        float4 s0 = reinterpret_cast<const float4*>(
            g_v + (size_t)(b * NC + c) * U_)[u4];
        h[0] = s0.x; h[1] = s0.y; h[2] = s0.z; h[3] = s0.w;

        uint2* p = reinterpret_cast<uint2*>(
            g_uh + (size_t)(b * L_ + c * CL) * U_) + u4;
        #pragma unroll 8
        for (int t = 0; t < CL; t++) {
            uint2 v2 = p[(size_t)t * (U_ / 4)];
            const __half2* hh = reinterpret_cast<const __half2*>(&v2);
            __half2 o[2];
            #pragma unroll
            for (int j = 0; j < 2; j++) {
                float2 f = __half22float2(hh[j]);
                h[2 * j]     = fmaf(lam[2 * j],     h[2 * j],     f.x);
                h[2 * j + 1] = fmaf(lam[2 * j + 1], h[2 * j + 1], f.y);
                o[j] = __floats2half2_rn(h[2 * j] * gam[2 * j],
                                         h[2 * j + 1] * gam[2 * j + 1]);
            }
            p[(size_t)t * (U_ / 4)] = *reinterpret_cast<uint2*>(o);
        }
    }
}

// ---------------- launch ------------------------------------------------------
extern "C" void kernel_launch(void* const* d_in, const int* in_sizes, int n_in,
                              void* d_out, int out_size)
{
    const float* inputs = (const float*)d_in[0];
    const float* Wi     = (const float*)d_in[1];
    const float* bi     = (const float*)d_in[2];
    const float* Wo     = (const float*)d_in[3];
    const float* bo     = (const float*)d_in[4];
    const float* plog   = (const float*)d_in[5];
    float* out = (float*)d_out;

    cudaFuncSetAttribute(gemm_f16_kernel,
                         cudaFuncAttributeMaxDynamicSharedMemorySize, GEMM_SMEM);

    // fp16 conversion (also resets the scan grid-barrier counters)
    cvt_all_kernel<<<2048, 256>>>((const float4*)inputs,
                                  (const float4*)Wi,
                                  (const float4*)Wo);

    // GEMM1: u = inputs * Wi^T + bi   -> g_uh (fp16)
    gemm_f16_kernel<<<dim3(U_ / TN, M_ / TM), 256, GEMM_SMEM>>>(0, bi, nullptr);

    // fused scan (agg -> carry -> apply), in place on g_uh
    scan_fused_kernel<<<256, 256>>>(plog);

    // GEMM2: out = x * Wo^T + bo
    gemm_f16_kernel<<<dim3(H_ / TN, M_ / TM), 256, GEMM_SMEM>>>(1, bo, out);
}